// round 11
// baseline (speedup 1.0000x reference)
#include <cuda_runtime.h>
#include <cuda_fp16.h>
#include <math.h>
#include <stdint.h>

#define OMEGA 1.5f
#define NROW  384
#define MID   256
#define NR    100     // rank R
#define RP    112     // padded rank (K dim for MMA), 7 x k16

// Factor matrices, row-major padded K: g_X[row*RP + r], r<100 valid, rest 0
__device__ float g_A[NROW * RP];
__device__ float g_B[NROW * RP];
__device__ __half g_Ch[NROW * RP];     // C rounded to fp16

// C-net middle hidden
__device__ float g_H2[NROW * MID];

// ===========================================================================
// helpers
// ===========================================================================
__device__ __forceinline__ uint32_t smem_u32(const void* p) {
    uint32_t a;
    asm("{ .reg .u64 t; cvta.to.shared.u64 t, %1; cvt.u32.u64 %0, t; }" : "=r"(a) : "l"(p));
    return a;
}
__device__ __forceinline__ void ldsm4(uint32_t addr, uint32_t r[4]) {
    asm volatile("ldmatrix.sync.aligned.m8n8.x4.shared.b16 {%0,%1,%2,%3}, [%4];"
                 : "=r"(r[0]), "=r"(r[1]), "=r"(r[2]), "=r"(r[3]) : "r"(addr));
}
__device__ __forceinline__ void mma16816(float d[4], const uint32_t* a,
                                         uint32_t b0, uint32_t b1) {
    asm volatile("mma.sync.aligned.m16n8k16.row.col.f32.f16.f16.f32 "
                 "{%0,%1,%2,%3}, {%4,%5,%6,%7}, {%8,%9}, {%0,%1,%2,%3};"
                 : "+f"(d[0]), "+f"(d[1]), "+f"(d[2]), "+f"(d[3])
                 : "r"(a[0]), "r"(a[1]), "r"(a[2]), "r"(a[3]), "r"(b0), "r"(b1));
}
__device__ __forceinline__ void cp16(uint32_t dst, const void* src) {
    asm volatile("cp.async.cg.shared.global [%0], [%1], 16;" :: "r"(dst), "l"(src));
}
#define CP_COMMIT() asm volatile("cp.async.commit_group;" ::: "memory")
#define CP_WAIT0()  asm volatile("cp.async.wait_group 0;" ::: "memory")

// ===========================================================================
// Factor networks. First sine layer computed INLINE in the GEMM load phase.
// ===========================================================================

// 32x32 tile GEMM core with H = sin(omega*(x_m * w1_k + b1_k)) inline.
__device__ __forceinline__ void gemm32_sine(const float* __restrict__ in,
                                            const float* __restrict__ W1,
                                            const float* __restrict__ b1,
                                            const float* __restrict__ W,
                                            int rb, int nb, int nout,
                                            float acc[2][2])
{
    __shared__ float sH[32][33];
    __shared__ float sW[32][33];
    const int tid = threadIdx.x;
    const int kk  = tid & 31;
    const int mm  = tid >> 5;
    const int tx  = tid & 15;
    const int ty  = tid >> 4;
    const int m0  = ty * 2;
    const int n0  = tx * 2;

    acc[0][0] = acc[0][1] = acc[1][0] = acc[1][1] = 0.f;

    for (int k0 = 0; k0 < MID; k0 += 32) {
        __syncthreads();
        const float w1 = W1[k0 + kk];
        const float bb = b1[k0 + kk];
        #pragma unroll
        for (int s = 0; s < 4; s++) {
            const int r = mm + s * 8;
            sH[r][kk] = sinf(OMEGA * (in[rb + r] * w1 + bb));
            const int n = nb + r;
            sW[r][kk] = (n < nout) ? W[n * MID + k0 + kk] : 0.f;
        }
        __syncthreads();
        #pragma unroll
        for (int k = 0; k < 32; k++) {
            const float h0 = sH[m0][k], h1 = sH[m0 + 1][k];
            const float w0 = sW[n0][k], w1v = sW[n0 + 1][k];
            acc[0][0] += h0 * w0; acc[0][1] += h0 * w1v;
            acc[1][0] += h1 * w0; acc[1][1] += h1 * w1v;
        }
    }
}

// 32x32 tile GEMM core reading H from memory.
__device__ __forceinline__ void gemm32_mem(const float* __restrict__ H,
                                           const float* __restrict__ W,
                                           int rb, int nb, int nout,
                                           float acc[2][2])
{
    __shared__ float sH[32][33];
    __shared__ float sW[32][33];
    const int tid = threadIdx.x;
    const int kk  = tid & 31;
    const int mm  = tid >> 5;
    const int tx  = tid & 15;
    const int ty  = tid >> 4;
    const int m0  = ty * 2;
    const int n0  = tx * 2;

    acc[0][0] = acc[0][1] = acc[1][0] = acc[1][1] = 0.f;

    for (int k0 = 0; k0 < MID; k0 += 32) {
        __syncthreads();
        #pragma unroll
        for (int s = 0; s < 4; s++) {
            const int r = mm + s * 8;
            sH[r][kk] = H[(rb + r) * MID + k0 + kk];
            const int n = nb + r;
            sW[r][kk] = (n < nout) ? W[n * MID + k0 + kk] : 0.f;
        }
        __syncthreads();
        #pragma unroll
        for (int k = 0; k < 32; k++) {
            const float h0 = sH[m0][k], h1 = sH[m0 + 1][k];
            const float w0 = sW[n0][k], w1 = sW[n0 + 1][k];
            acc[0][0] += h0 * w0; acc[0][1] += h0 * w1;
            acc[1][0] += h1 * w0; acc[1][1] += h1 * w1;
        }
    }
}

// C-net middle layer: g_H2 = sin(omega*(H_C @ CW2^T + Cb2)), H_C inline.
__global__ void __launch_bounds__(256) mid_gemm_kernel(const float* __restrict__ Cin,
                                                       const float* __restrict__ CW1,
                                                       const float* __restrict__ Cb1,
                                                       const float* __restrict__ CW2,
                                                       const float* __restrict__ Cb2)
{
    const int rb = blockIdx.y * 32;
    const int nb = blockIdx.x * 32;
    float acc[2][2];
    gemm32_sine(Cin, CW1, Cb1, CW2, rb, nb, MID, acc);
    const int tx = threadIdx.x & 15, ty = threadIdx.x >> 4;
    #pragma unroll
    for (int i = 0; i < 2; i++) {
        const int m = rb + ty * 2 + i;
        #pragma unroll
        for (int j = 0; j < 2; j++) {
            const int n = nb + tx * 2 + j;
            g_H2[m * MID + n] = sinf(OMEGA * (acc[i][j] + Cb2[n]));
        }
    }
}

// Final layers: A/B with inline first layer; C from g_H2.
__global__ void __launch_bounds__(256) final_gemm_kernel(
    const float* __restrict__ A_in, const float* __restrict__ AW1,
    const float* __restrict__ Ab1,  const float* __restrict__ AW2,
    const float* __restrict__ Ab2,
    const float* __restrict__ B_in, const float* __restrict__ BW1,
    const float* __restrict__ Bb1,  const float* __restrict__ BW2,
    const float* __restrict__ Bb2,
    const float* __restrict__ CW3,  const float* __restrict__ Cb3)
{
    const int net = blockIdx.z;
    const int rb  = blockIdx.y * 32;
    const int nb  = blockIdx.x * 32;

    float acc[2][2];
    const float* b;
    if (net == 0) { gemm32_sine(A_in, AW1, Ab1, AW2, rb, nb, NR, acc); b = Ab2; }
    else if (net == 1) { gemm32_sine(B_in, BW1, Bb1, BW2, rb, nb, NR, acc); b = Bb2; }
    else { gemm32_mem(g_H2, CW3, rb, nb, NR, acc); b = Cb3; }

    const int tx = threadIdx.x & 15, ty = threadIdx.x >> 4;
    #pragma unroll
    for (int i = 0; i < 2; i++) {
        const int m = rb + ty * 2 + i;
        #pragma unroll
        for (int j = 0; j < 2; j++) {
            const int n = nb + tx * 2 + j;
            if (n < NR) {
                const float v = acc[i][j] + b[n];
                if (net == 0)      g_A[m * RP + n] = v;
                else if (net == 1) g_B[m * RP + n] = v;
                else               g_Ch[m * RP + n] = __float2half_rn(v);
            }
        }
    }
}

// ===========================================================================
// Contraction: HMMA fp16 SINGLE pass (M and C each rounded once to fp16).
// Block 256 = 8 warps (4m x 2n), warp tile 32(j) x 64(k).
// CTA = (jb, i): 128j x 384k as 3 kb iterations of 128k.
// Per k-step per warp: 6 ldsm4 (a x2, b x4) -> 16 MMAs.
// smem: M 30KB + C 2x30KB double-buffered = 90KB -> 2 CTAs/SM.
// ===========================================================================
#define LDB 240
#define MT  (128 * LDB)              // 30720: [128 x 112] fp16 tile
#define OFF_M 0
#define OFF_C MT                     // + buf*MT
#define SMEM_NEED (3 * MT)           // 92160 bytes

__device__ __forceinline__ void prefetch_C(uint32_t sb, int kt, int buf, int tid) {
    const uint32_t dst0 = sb + OFF_C + (uint32_t)(buf * MT);
    #pragma unroll
    for (int it = 0; it < 7; it++) {
        const int idx = tid + it * 256;          // 0..1791 = 128 rows x 14 chunks
        const int row = idx / 14;
        const int ch  = idx % 14;
        const __half* src = g_Ch + (kt * 128 + row) * RP + ch * 8;
        cp16(dst0 + (uint32_t)(row * LDB + ch * 16), src);
    }
}

__global__ void __launch_bounds__(256, 2) contract_kernel(float* __restrict__ out)
{
    extern __shared__ __align__(16) char sm[];
    const uint32_t sbase = smem_u32(sm);

    const int tid  = threadIdx.x;
    const int lane = tid & 31;
    const int wid  = tid >> 5;
    const int i    = blockIdx.y;
    const int jb   = blockIdx.x * 128;

    const int wm = (wid & 3) * 32;    // m (j) offset
    const int wn = (wid >> 2) * 64;   // n (k) offset within kb tile

    // prefetch C tile 0, then convert M = A[i,:] * B[jb:,:] into fp16
    prefetch_C(sbase, 0, 0, tid);
    CP_COMMIT();

    #pragma unroll
    for (int it = 0; it < 28; it++) {
        const int idx = tid + it * 256;          // 0..7167 = 128 x 56
        const int j  = idx / 56;
        const int pr = idx % 56;
        const int r0 = pr * 2;
        float2 bv = make_float2(0.f, 0.f), av = make_float2(0.f, 0.f);
        if (pr < 50) {
            bv = *reinterpret_cast<const float2*>(&g_B[(jb + j) * RP + r0]);
            av = *reinterpret_cast<const float2*>(&g_A[i * RP + r0]);
        }
        const __half h0 = __float2half_rn(av.x * bv.x);
        const __half h1 = __float2half_rn(av.y * bv.y);
        const uint32_t hv = (uint32_t)__half_as_ushort(h0)
                          | ((uint32_t)__half_as_ushort(h1) << 16);
        *reinterpret_cast<uint32_t*>(sm + OFF_M + (uint32_t)(j * LDB + pr * 4)) = hv;
    }
    CP_WAIT0();
    __syncthreads();

    // fragment lane addresses
    const uint32_t aoff = (uint32_t)((lane & 15) * LDB + (lane >> 4) * 16);
    const uint32_t boff = (uint32_t)(((lane & 7) + ((lane >> 4) << 3)) * LDB
                                     + ((lane >> 3) & 1) * 16);
    const uint32_t mA = sbase + OFF_M + (uint32_t)(wm * LDB) + aoff;

    float acc[16][4];
    #pragma unroll
    for (int t = 0; t < 16; t++)
        #pragma unroll
        for (int q = 0; q < 4; q++) acc[t][q] = 0.f;

    const int g  = lane >> 2;
    const int c2 = (lane & 3) * 2;

    for (int kb = 0; kb < 3; kb++) {
        // start async load of next C k-tile (overlaps this kb's MMAs)
        if (kb < 2) { prefetch_C(sbase, kb + 1, (kb + 1) & 1, tid); CP_COMMIT(); }

        const uint32_t Bb = sbase + OFF_C + (uint32_t)((kb & 1) * MT)
                           + (uint32_t)(wn * LDB) + boff;

        #pragma unroll
        for (int ks = 0; ks < 7; ks++) {
            uint32_t ah[8], bh[16];
            ldsm4(mA + ks * 32, ah);
            ldsm4(mA + 16 * LDB + ks * 32, ah + 4);
            #pragma unroll
            for (int p = 0; p < 4; p++)
                ldsm4(Bb + (uint32_t)(p * 16 * LDB) + ks * 32, bh + 4 * p);
            #pragma unroll
            for (int nt = 0; nt < 8; nt++) {
                const uint32_t b0 = bh[nt * 2], b1 = bh[nt * 2 + 1];
                mma16816(acc[nt],     ah,     b0, b1);
                mma16816(acc[8 + nt], ah + 4, b0, b1);
            }
        }

        // store this 128-k tile, reset acc
        #pragma unroll
        for (int mt = 0; mt < 2; mt++) {
            #pragma unroll
            for (int nt = 0; nt < 8; nt++) {
                float* p = out + ((size_t)i * NROW + (size_t)(jb + wm + mt * 16 + g)) * NROW
                               + (size_t)(kb * 128 + wn + nt * 8 + c2);
                float* a = acc[mt * 8 + nt];
                *reinterpret_cast<float2*>(p) = make_float2(a[0], a[1]);
                *reinterpret_cast<float2*>(p + (size_t)8 * NROW) = make_float2(a[2], a[3]);
                a[0] = a[1] = a[2] = a[3] = 0.f;
            }
        }

        if (kb < 2) { CP_WAIT0(); __syncthreads(); }
    }
}

// ===========================================================================
// kernel_launch
// ===========================================================================
extern "C" void kernel_launch(void* const* d_in, const int* in_sizes, int n_in,
                              void* d_out, int out_size)
{
    const float* A_in = (const float*)d_in[0];
    const float* B_in = (const float*)d_in[1];
    const float* C_in = (const float*)d_in[2];
    const float* A_W1 = (const float*)d_in[3];
    const float* A_b1 = (const float*)d_in[4];
    const float* A_W2 = (const float*)d_in[5];
    const float* A_b2 = (const float*)d_in[6];
    const float* B_W1 = (const float*)d_in[7];
    const float* B_b1 = (const float*)d_in[8];
    const float* B_W2 = (const float*)d_in[9];
    const float* B_b2 = (const float*)d_in[10];
    const float* C_W1 = (const float*)d_in[11];
    const float* C_b1 = (const float*)d_in[12];
    const float* C_W2 = (const float*)d_in[13];
    const float* C_b2 = (const float*)d_in[14];
    const float* C_W3 = (const float*)d_in[15];
    const float* C_b3 = (const float*)d_in[16];

    float* out = (float*)d_out;

    cudaFuncSetAttribute(contract_kernel,
                         cudaFuncAttributeMaxDynamicSharedMemorySize, SMEM_NEED);

    dim3 g2(MID / 32, NROW / 32);                  // (8, 12)
    mid_gemm_kernel<<<g2, 256>>>(C_in, C_W1, C_b1, C_W2, C_b2);

    dim3 g3((NR + 31) / 32, NROW / 32, 3);         // (4, 12, 3)
    final_gemm_kernel<<<g3, 256>>>(A_in, A_W1, A_b1, A_W2, A_b2,
                                   B_in, B_W1, B_b1, B_W2, B_b2,
                                   C_W3, C_b3);

    dim3 grid(NROW / 128, NROW);                   // (3 j-tiles, 384 i)
    contract_kernel<<<grid, 256, SMEM_NEED>>>(out);
}

// round 12
// speedup vs baseline: 1.2223x; 1.2223x over previous
#include <cuda_runtime.h>
#include <cuda_fp16.h>
#include <math.h>
#include <stdint.h>

#define OMEGA 1.5f
#define NROW  384
#define MID   256
#define NR    100     // rank R
#define RP    112     // padded rank (K dim for MMA), 7 x k16

// Factor matrices, row-major padded K: g_X[row*RP + r], r<100 valid, rest 0
__device__ float g_A[NROW * RP];
__device__ float g_B[NROW * RP];
__device__ __half g_Ch[NROW * RP];     // C rounded to fp16

// MLP intermediates
__device__ float g_H[3 * NROW * MID];
__device__ float g_H2[NROW * MID];

// ===========================================================================
// helpers
// ===========================================================================
__device__ __forceinline__ uint32_t smem_u32(const void* p) {
    uint32_t a;
    asm("{ .reg .u64 t; cvta.to.shared.u64 t, %1; cvt.u32.u64 %0, t; }" : "=r"(a) : "l"(p));
    return a;
}
__device__ __forceinline__ void ldsm4(uint32_t addr, uint32_t r[4]) {
    asm volatile("ldmatrix.sync.aligned.m8n8.x4.shared.b16 {%0,%1,%2,%3}, [%4];"
                 : "=r"(r[0]), "=r"(r[1]), "=r"(r[2]), "=r"(r[3]) : "r"(addr));
}
__device__ __forceinline__ void mma16816(float d[4], const uint32_t* a,
                                         uint32_t b0, uint32_t b1) {
    asm volatile("mma.sync.aligned.m16n8k16.row.col.f32.f16.f16.f32 "
                 "{%0,%1,%2,%3}, {%4,%5,%6,%7}, {%8,%9}, {%0,%1,%2,%3};"
                 : "+f"(d[0]), "+f"(d[1]), "+f"(d[2]), "+f"(d[3])
                 : "r"(a[0]), "r"(a[1]), "r"(a[2]), "r"(a[3]), "r"(b0), "r"(b1));
}
__device__ __forceinline__ void cp16(uint32_t dst, const void* src) {
    asm volatile("cp.async.cg.shared.global [%0], [%1], 16;" :: "r"(dst), "l"(src));
}
#define CP_COMMIT() asm volatile("cp.async.commit_group;" ::: "memory")
#define CP_WAIT0()  asm volatile("cp.async.wait_group 0;" ::: "memory")

// ===========================================================================
// Factor networks (R9 structure: precomputed hidden layer, memory GEMMs)
// ===========================================================================
__global__ void hidden_kernel(const float* __restrict__ Ain,
                              const float* __restrict__ Bin,
                              const float* __restrict__ Cin,
                              const float* __restrict__ AW1, const float* __restrict__ Ab1,
                              const float* __restrict__ BW1, const float* __restrict__ Bb1,
                              const float* __restrict__ CW1, const float* __restrict__ Cb1)
{
    const int net = blockIdx.y;
    const int row = blockIdx.x;
    const int t   = threadIdx.x;
    const float x = (net == 0 ? Ain : net == 1 ? Bin : Cin)[row];
    const float* W1 = (net == 0 ? AW1 : net == 1 ? BW1 : CW1);
    const float* b1 = (net == 0 ? Ab1 : net == 1 ? Bb1 : Cb1);
    g_H[(net * NROW + row) * MID + t] = sinf(OMEGA * (x * W1[t] + b1[t]));
}

// 32x32 tile GEMM core, 256 threads, micro 2x2.
__device__ __forceinline__ void gemm32(const float* __restrict__ H,
                                       const float* __restrict__ W,
                                       int rb, int nb, int nout,
                                       float acc[2][2])
{
    __shared__ float sH[32][33];
    __shared__ float sW[32][33];
    const int tid = threadIdx.x;
    const int kk  = tid & 31;
    const int mm  = tid >> 5;        // 0..7
    const int tx  = tid & 15;
    const int ty  = tid >> 4;
    const int m0  = ty * 2;
    const int n0  = tx * 2;

    acc[0][0] = acc[0][1] = acc[1][0] = acc[1][1] = 0.f;

    for (int k0 = 0; k0 < MID; k0 += 32) {
        __syncthreads();
        #pragma unroll
        for (int s = 0; s < 4; s++) {
            const int r = mm + s * 8;
            sH[r][kk] = H[(rb + r) * MID + k0 + kk];
            const int n = nb + r;
            sW[r][kk] = (n < nout) ? W[n * MID + k0 + kk] : 0.f;
        }
        __syncthreads();
        #pragma unroll
        for (int k = 0; k < 32; k++) {
            const float h0 = sH[m0][k], h1 = sH[m0 + 1][k];
            const float w0 = sW[n0][k], w1 = sW[n0 + 1][k];
            acc[0][0] += h0 * w0; acc[0][1] += h0 * w1;
            acc[1][0] += h1 * w0; acc[1][1] += h1 * w1;
        }
    }
}

__global__ void __launch_bounds__(256) mid_gemm_kernel(const float* __restrict__ CW2,
                                                       const float* __restrict__ Cb2)
{
    const int rb = blockIdx.y * 32;
    const int nb = blockIdx.x * 32;
    float acc[2][2];
    gemm32(g_H + 2 * NROW * MID, CW2, rb, nb, MID, acc);
    const int tx = threadIdx.x & 15, ty = threadIdx.x >> 4;
    #pragma unroll
    for (int i = 0; i < 2; i++) {
        const int m = rb + ty * 2 + i;
        #pragma unroll
        for (int j = 0; j < 2; j++) {
            const int n = nb + tx * 2 + j;
            g_H2[m * MID + n] = sinf(OMEGA * (acc[i][j] + Cb2[n]));
        }
    }
}

__global__ void __launch_bounds__(256) final_gemm_kernel(const float* __restrict__ AW2,
                                                         const float* __restrict__ Ab2,
                                                         const float* __restrict__ BW2,
                                                         const float* __restrict__ Bb2,
                                                         const float* __restrict__ CW3,
                                                         const float* __restrict__ Cb3)
{
    const int net = blockIdx.z;
    const int rb  = blockIdx.y * 32;
    const int nb  = blockIdx.x * 32;
    const float* H = (net == 2) ? g_H2 : g_H + net * NROW * MID;
    const float* W = (net == 0) ? AW2 : (net == 1) ? BW2 : CW3;
    const float* b = (net == 0) ? Ab2 : (net == 1) ? Bb2 : Cb3;

    float acc[2][2];
    gemm32(H, W, rb, nb, NR, acc);
    const int tx = threadIdx.x & 15, ty = threadIdx.x >> 4;
    #pragma unroll
    for (int i = 0; i < 2; i++) {
        const int m = rb + ty * 2 + i;
        #pragma unroll
        for (int j = 0; j < 2; j++) {
            const int n = nb + tx * 2 + j;
            if (n < NR) {
                const float v = acc[i][j] + b[n];
                if (net == 0)      g_A[m * RP + n] = v;
                else if (net == 1) g_B[m * RP + n] = v;
                else               g_Ch[m * RP + n] = __float2half_rn(v);
            }
        }
    }
}

// ===========================================================================
// Contraction: HMMA fp16 SINGLE pass (M and C each rounded once to fp16).
// Block 256 = 8 warps (4m x 2n), warp tile 32(j) x 64(k).
// CTA = (jb, i): 128j x 384k as 3 kb iterations of 128k.
// Per k-step per warp: 6 ldsm4 (a x2, b x4) -> 16 MMAs.
// smem: M 30KB + C 2x30KB double-buffered = 90KB -> 2 CTAs/SM.
// ===========================================================================
#define LDB 240
#define MT  (128 * LDB)              // 30720: [128 x 112] fp16 tile
#define OFF_M 0
#define OFF_C MT                     // + buf*MT
#define SMEM_NEED (3 * MT)           // 92160 bytes

__device__ __forceinline__ void prefetch_C(uint32_t sb, int kt, int buf, int tid) {
    const uint32_t dst0 = sb + OFF_C + (uint32_t)(buf * MT);
    #pragma unroll
    for (int it = 0; it < 7; it++) {
        const int idx = tid + it * 256;          // 0..1791 = 128 rows x 14 chunks
        const int row = idx / 14;
        const int ch  = idx % 14;
        const __half* src = g_Ch + (kt * 128 + row) * RP + ch * 8;
        cp16(dst0 + (uint32_t)(row * LDB + ch * 16), src);
    }
}

__global__ void __launch_bounds__(256, 2) contract_kernel(float* __restrict__ out)
{
    extern __shared__ __align__(16) char sm[];
    const uint32_t sbase = smem_u32(sm);

    const int tid  = threadIdx.x;
    const int lane = tid & 31;
    const int wid  = tid >> 5;
    const int i    = blockIdx.y;
    const int jb   = blockIdx.x * 128;

    const int wm = (wid & 3) * 32;    // m (j) offset
    const int wn = (wid >> 2) * 64;   // n (k) offset within kb tile

    // prefetch C tile 0, then convert M = A[i,:] * B[jb:,:] into fp16
    prefetch_C(sbase, 0, 0, tid);
    CP_COMMIT();

    #pragma unroll
    for (int it = 0; it < 28; it++) {
        const int idx = tid + it * 256;          // 0..7167 = 128 x 56
        const int j  = idx / 56;
        const int pr = idx % 56;
        const int r0 = pr * 2;
        float2 bv = make_float2(0.f, 0.f), av = make_float2(0.f, 0.f);
        if (pr < 50) {
            bv = *reinterpret_cast<const float2*>(&g_B[(jb + j) * RP + r0]);
            av = *reinterpret_cast<const float2*>(&g_A[i * RP + r0]);
        }
        const __half h0 = __float2half_rn(av.x * bv.x);
        const __half h1 = __float2half_rn(av.y * bv.y);
        const uint32_t hv = (uint32_t)__half_as_ushort(h0)
                          | ((uint32_t)__half_as_ushort(h1) << 16);
        *reinterpret_cast<uint32_t*>(sm + OFF_M + (uint32_t)(j * LDB + pr * 4)) = hv;
    }
    CP_WAIT0();
    __syncthreads();

    // fragment lane addresses
    const uint32_t aoff = (uint32_t)((lane & 15) * LDB + (lane >> 4) * 16);
    const uint32_t boff = (uint32_t)(((lane & 7) + ((lane >> 4) << 3)) * LDB
                                     + ((lane >> 3) & 1) * 16);
    const uint32_t mA = sbase + OFF_M + (uint32_t)(wm * LDB) + aoff;

    float acc[16][4];
    #pragma unroll
    for (int t = 0; t < 16; t++)
        #pragma unroll
        for (int q = 0; q < 4; q++) acc[t][q] = 0.f;

    const int g  = lane >> 2;
    const int c2 = (lane & 3) * 2;

    for (int kb = 0; kb < 3; kb++) {
        // start async load of next C k-tile (overlaps this kb's MMAs)
        if (kb < 2) { prefetch_C(sbase, kb + 1, (kb + 1) & 1, tid); CP_COMMIT(); }

        const uint32_t Bb = sbase + OFF_C + (uint32_t)((kb & 1) * MT)
                           + (uint32_t)(wn * LDB) + boff;

        #pragma unroll
        for (int ks = 0; ks < 7; ks++) {
            uint32_t ah[8], bh[16];
            ldsm4(mA + ks * 32, ah);
            ldsm4(mA + 16 * LDB + ks * 32, ah + 4);
            #pragma unroll
            for (int p = 0; p < 4; p++)
                ldsm4(Bb + (uint32_t)(p * 16 * LDB) + ks * 32, bh + 4 * p);
            #pragma unroll
            for (int nt = 0; nt < 8; nt++) {
                const uint32_t b0 = bh[nt * 2], b1 = bh[nt * 2 + 1];
                mma16816(acc[nt],     ah,     b0, b1);
                mma16816(acc[8 + nt], ah + 4, b0, b1);
            }
        }

        // store this 128-k tile, reset acc
        #pragma unroll
        for (int mt = 0; mt < 2; mt++) {
            #pragma unroll
            for (int nt = 0; nt < 8; nt++) {
                float* p = out + ((size_t)i * NROW + (size_t)(jb + wm + mt * 16 + g)) * NROW
                               + (size_t)(kb * 128 + wn + nt * 8 + c2);
                float* a = acc[mt * 8 + nt];
                *reinterpret_cast<float2*>(p) = make_float2(a[0], a[1]);
                *reinterpret_cast<float2*>(p + (size_t)8 * NROW) = make_float2(a[2], a[3]);
                a[0] = a[1] = a[2] = a[3] = 0.f;
            }
        }

        if (kb < 2) { CP_WAIT0(); __syncthreads(); }
    }
}

// ===========================================================================
// kernel_launch
// ===========================================================================
extern "C" void kernel_launch(void* const* d_in, const int* in_sizes, int n_in,
                              void* d_out, int out_size)
{
    const float* A_in = (const float*)d_in[0];
    const float* B_in = (const float*)d_in[1];
    const float* C_in = (const float*)d_in[2];
    const float* A_W1 = (const float*)d_in[3];
    const float* A_b1 = (const float*)d_in[4];
    const float* A_W2 = (const float*)d_in[5];
    const float* A_b2 = (const float*)d_in[6];
    const float* B_W1 = (const float*)d_in[7];
    const float* B_b1 = (const float*)d_in[8];
    const float* B_W2 = (const float*)d_in[9];
    const float* B_b2 = (const float*)d_in[10];
    const float* C_W1 = (const float*)d_in[11];
    const float* C_b1 = (const float*)d_in[12];
    const float* C_W2 = (const float*)d_in[13];
    const float* C_b2 = (const float*)d_in[14];
    const float* C_W3 = (const float*)d_in[15];
    const float* C_b3 = (const float*)d_in[16];

    float* out = (float*)d_out;

    cudaFuncSetAttribute(contract_kernel,
                         cudaFuncAttributeMaxDynamicSharedMemorySize, SMEM_NEED);

    dim3 g1(NROW, 3);
    hidden_kernel<<<g1, MID>>>(A_in, B_in, C_in, A_W1, A_b1, B_W1, B_b1, C_W1, C_b1);

    dim3 g2(MID / 32, NROW / 32);                  // (8, 12)
    mid_gemm_kernel<<<g2, 256>>>(C_W2, C_b2);

    dim3 g3((NR + 31) / 32, NROW / 32, 3);         // (4, 12, 3)
    final_gemm_kernel<<<g3, 256>>>(A_W2, A_b2, B_W2, B_b2, C_W3, C_b3);

    dim3 grid(NROW / 128, NROW);                   // (3 j-tiles, 384 i)
    contract_kernel<<<grid, 256, SMEM_NEED>>>(out);
}

// round 13
// speedup vs baseline: 1.2314x; 1.0075x over previous
#include <cuda_runtime.h>
#include <cuda_fp16.h>
#include <math.h>
#include <stdint.h>

#define OMEGA 1.5f
#define NROW  384
#define MID   256
#define NR    100     // rank R
#define RP    112     // padded rank (K dim for MMA), 7 x k16

// Factor matrices, row-major padded K: g_X[row*RP + r], r<100 valid, rest 0
__device__ float g_A[NROW * RP];
__device__ float g_B[NROW * RP];
__device__ __half g_Ch[NROW * RP];     // C rounded to fp16

// MLP intermediates
__device__ float g_H[3 * NROW * MID];
__device__ float g_H2[NROW * MID];

// ===========================================================================
// helpers
// ===========================================================================
__device__ __forceinline__ uint32_t smem_u32(const void* p) {
    uint32_t a;
    asm("{ .reg .u64 t; cvta.to.shared.u64 t, %1; cvt.u32.u64 %0, t; }" : "=r"(a) : "l"(p));
    return a;
}
__device__ __forceinline__ void ldsm4(uint32_t addr, uint32_t r[4]) {
    asm volatile("ldmatrix.sync.aligned.m8n8.x4.shared.b16 {%0,%1,%2,%3}, [%4];"
                 : "=r"(r[0]), "=r"(r[1]), "=r"(r[2]), "=r"(r[3]) : "r"(addr));
}
__device__ __forceinline__ void mma16816(float d[4], const uint32_t* a,
                                         uint32_t b0, uint32_t b1) {
    asm volatile("mma.sync.aligned.m16n8k16.row.col.f32.f16.f16.f32 "
                 "{%0,%1,%2,%3}, {%4,%5,%6,%7}, {%8,%9}, {%0,%1,%2,%3};"
                 : "+f"(d[0]), "+f"(d[1]), "+f"(d[2]), "+f"(d[3])
                 : "r"(a[0]), "r"(a[1]), "r"(a[2]), "r"(a[3]), "r"(b0), "r"(b1));
}
__device__ __forceinline__ void cp16(uint32_t dst, const void* src) {
    asm volatile("cp.async.cg.shared.global [%0], [%1], 16;" :: "r"(dst), "l"(src));
}
#define CP_COMMIT() asm volatile("cp.async.commit_group;" ::: "memory")
#define CP_WAIT0()  asm volatile("cp.async.wait_group 0;" ::: "memory")

// ===========================================================================
// Factor networks (precomputed hidden layer, memory GEMMs)
// ===========================================================================
__global__ void hidden_kernel(const float* __restrict__ Ain,
                              const float* __restrict__ Bin,
                              const float* __restrict__ Cin,
                              const float* __restrict__ AW1, const float* __restrict__ Ab1,
                              const float* __restrict__ BW1, const float* __restrict__ Bb1,
                              const float* __restrict__ CW1, const float* __restrict__ Cb1)
{
    const int net = blockIdx.y;
    const int row = blockIdx.x;
    const int t   = threadIdx.x;
    const float x = (net == 0 ? Ain : net == 1 ? Bin : Cin)[row];
    const float* W1 = (net == 0 ? AW1 : net == 1 ? BW1 : CW1);
    const float* b1 = (net == 0 ? Ab1 : net == 1 ? Bb1 : Cb1);
    g_H[(net * NROW + row) * MID + t] = sinf(OMEGA * (x * W1[t] + b1[t]));
}

// 32x32 tile GEMM core, 256 threads, micro 2x2.
__device__ __forceinline__ void gemm32(const float* __restrict__ H,
                                       const float* __restrict__ W,
                                       int rb, int nb, int nout,
                                       float acc[2][2])
{
    __shared__ float sH[32][33];
    __shared__ float sW[32][33];
    const int tid = threadIdx.x;
    const int kk  = tid & 31;
    const int mm  = tid >> 5;        // 0..7
    const int tx  = tid & 15;
    const int ty  = tid >> 4;
    const int m0  = ty * 2;
    const int n0  = tx * 2;

    acc[0][0] = acc[0][1] = acc[1][0] = acc[1][1] = 0.f;

    for (int k0 = 0; k0 < MID; k0 += 32) {
        __syncthreads();
        #pragma unroll
        for (int s = 0; s < 4; s++) {
            const int r = mm + s * 8;
            sH[r][kk] = H[(rb + r) * MID + k0 + kk];
            const int n = nb + r;
            sW[r][kk] = (n < nout) ? W[n * MID + k0 + kk] : 0.f;
        }
        __syncthreads();
        #pragma unroll
        for (int k = 0; k < 32; k++) {
            const float h0 = sH[m0][k], h1 = sH[m0 + 1][k];
            const float w0 = sW[n0][k], w1 = sW[n0 + 1][k];
            acc[0][0] += h0 * w0; acc[0][1] += h0 * w1;
            acc[1][0] += h1 * w0; acc[1][1] += h1 * w1;
        }
    }
}

__global__ void __launch_bounds__(256) mid_gemm_kernel(const float* __restrict__ CW2,
                                                       const float* __restrict__ Cb2)
{
    const int rb = blockIdx.y * 32;
    const int nb = blockIdx.x * 32;
    float acc[2][2];
    gemm32(g_H + 2 * NROW * MID, CW2, rb, nb, MID, acc);
    const int tx = threadIdx.x & 15, ty = threadIdx.x >> 4;
    #pragma unroll
    for (int i = 0; i < 2; i++) {
        const int m = rb + ty * 2 + i;
        #pragma unroll
        for (int j = 0; j < 2; j++) {
            const int n = nb + tx * 2 + j;
            g_H2[m * MID + n] = sinf(OMEGA * (acc[i][j] + Cb2[n]));
        }
    }
}

__global__ void __launch_bounds__(256) final_gemm_kernel(const float* __restrict__ AW2,
                                                         const float* __restrict__ Ab2,
                                                         const float* __restrict__ BW2,
                                                         const float* __restrict__ Bb2,
                                                         const float* __restrict__ CW3,
                                                         const float* __restrict__ Cb3)
{
    const int net = blockIdx.z;
    const int rb  = blockIdx.y * 32;
    const int nb  = blockIdx.x * 32;
    const float* H = (net == 2) ? g_H2 : g_H + net * NROW * MID;
    const float* W = (net == 0) ? AW2 : (net == 1) ? BW2 : CW3;
    const float* b = (net == 0) ? Ab2 : (net == 1) ? Bb2 : Cb3;

    float acc[2][2];
    gemm32(H, W, rb, nb, NR, acc);
    const int tx = threadIdx.x & 15, ty = threadIdx.x >> 4;
    #pragma unroll
    for (int i = 0; i < 2; i++) {
        const int m = rb + ty * 2 + i;
        #pragma unroll
        for (int j = 0; j < 2; j++) {
            const int n = nb + tx * 2 + j;
            if (n < NR) {
                const float v = acc[i][j] + b[n];
                if (net == 0)      g_A[m * RP + n] = v;
                else if (net == 1) g_B[m * RP + n] = v;
                else               g_Ch[m * RP + n] = __float2half_rn(v);
            }
        }
    }
}

// ===========================================================================
// Contraction: HMMA fp16 single pass, 3 CTAs/SM for latency hiding.
// Block 256 = 8 warps (4m x 2n), warp tile 32(j) x 32(k).
// CTA = (jb, i): 128j x 384k as 6 kb iterations of 64k.
// Per k-step per warp: 4 ldsm4 -> 8 MMAs.
// smem: M 30KB + C 2x15KB (64-row tiles, double-buffered) = 61440 -> 3 CTAs/SM.
// ===========================================================================
#define LDB 240
#define MT  (128 * LDB)              // 30720: [128 x 112] fp16 M tile
#define CT  (64 * LDB)               // 15360: [64 x 112] fp16 C k-tile
#define OFF_M 0
#define OFF_C MT                     // + buf*CT
#define SMEM_NEED (MT + 2 * CT)      // 61440 bytes

__device__ __forceinline__ void prefetch_C(uint32_t sb, int kt, int buf, int tid) {
    const uint32_t dst0 = sb + OFF_C + (uint32_t)(buf * CT);
    #pragma unroll
    for (int it = 0; it < 4; it++) {
        const int idx = tid + it * 256;          // need 0..895 = 64 rows x 14 chunks
        if (idx < 64 * 14) {
            const int row = idx / 14;
            const int ch  = idx % 14;
            const __half* src = g_Ch + (kt * 64 + row) * RP + ch * 8;
            cp16(dst0 + (uint32_t)(row * LDB + ch * 16), src);
        }
    }
}

__global__ void __launch_bounds__(256, 3) contract_kernel(float* __restrict__ out)
{
    extern __shared__ __align__(16) char sm[];
    const uint32_t sbase = smem_u32(sm);

    const int tid  = threadIdx.x;
    const int lane = tid & 31;
    const int wid  = tid >> 5;
    const int i    = blockIdx.y;
    const int jb   = blockIdx.x * 128;

    const int wm = (wid & 3) * 32;    // m (j) offset
    const int wn = (wid >> 2) * 32;   // n (k) offset within 64-k tile

    // prefetch C k-tile 0, then convert M = A[i,:] * B[jb:,:] into fp16
    prefetch_C(sbase, 0, 0, tid);
    CP_COMMIT();

    #pragma unroll
    for (int it = 0; it < 28; it++) {
        const int idx = tid + it * 256;          // 0..7167 = 128 x 56
        const int j  = idx / 56;
        const int pr = idx % 56;
        const int r0 = pr * 2;
        float2 bv = make_float2(0.f, 0.f), av = make_float2(0.f, 0.f);
        if (pr < 50) {
            bv = *reinterpret_cast<const float2*>(&g_B[(jb + j) * RP + r0]);
            av = *reinterpret_cast<const float2*>(&g_A[i * RP + r0]);
        }
        const __half h0 = __float2half_rn(av.x * bv.x);
        const __half h1 = __float2half_rn(av.y * bv.y);
        const uint32_t hv = (uint32_t)__half_as_ushort(h0)
                          | ((uint32_t)__half_as_ushort(h1) << 16);
        *reinterpret_cast<uint32_t*>(sm + OFF_M + (uint32_t)(j * LDB + pr * 4)) = hv;
    }
    CP_WAIT0();
    __syncthreads();

    // fragment lane addresses
    const uint32_t aoff = (uint32_t)((lane & 15) * LDB + (lane >> 4) * 16);
    const uint32_t boff = (uint32_t)(((lane & 7) + ((lane >> 4) << 3)) * LDB
                                     + ((lane >> 3) & 1) * 16);
    const uint32_t mA = sbase + OFF_M + (uint32_t)(wm * LDB) + aoff;

    float acc[8][4];
    #pragma unroll
    for (int t = 0; t < 8; t++)
        #pragma unroll
        for (int q = 0; q < 4; q++) acc[t][q] = 0.f;

    const int g  = lane >> 2;
    const int c2 = (lane & 3) * 2;

    for (int kb = 0; kb < 6; kb++) {
        // start async load of next C k-tile (overlaps this kb's MMAs)
        if (kb < 5) { prefetch_C(sbase, kb + 1, (kb + 1) & 1, tid); CP_COMMIT(); }

        const uint32_t Bb = sbase + OFF_C + (uint32_t)((kb & 1) * CT)
                           + (uint32_t)(wn * LDB) + boff;

        #pragma unroll
        for (int ks = 0; ks < 7; ks++) {
            uint32_t ah[8], bh[8];
            ldsm4(mA + ks * 32, ah);
            ldsm4(mA + 16 * LDB + ks * 32, ah + 4);
            ldsm4(Bb + ks * 32, bh);
            ldsm4(Bb + 16 * LDB + ks * 32, bh + 4);
            #pragma unroll
            for (int nt = 0; nt < 4; nt++) {
                const uint32_t b0 = bh[nt * 2], b1 = bh[nt * 2 + 1];
                mma16816(acc[nt],     ah,     b0, b1);
                mma16816(acc[4 + nt], ah + 4, b0, b1);
            }
        }

        // store this 64-k tile, reset acc
        #pragma unroll
        for (int mt = 0; mt < 2; mt++) {
            #pragma unroll
            for (int nt = 0; nt < 4; nt++) {
                float* p = out + ((size_t)i * NROW + (size_t)(jb + wm + mt * 16 + g)) * NROW
                               + (size_t)(kb * 64 + wn + nt * 8 + c2);
                float* a = acc[mt * 4 + nt];
                *reinterpret_cast<float2*>(p) = make_float2(a[0], a[1]);
                *reinterpret_cast<float2*>(p + (size_t)8 * NROW) = make_float2(a[2], a[3]);
                a[0] = a[1] = a[2] = a[3] = 0.f;
            }
        }

        if (kb < 5) { CP_WAIT0(); __syncthreads(); }
    }
}

// ===========================================================================
// kernel_launch
// ===========================================================================
extern "C" void kernel_launch(void* const* d_in, const int* in_sizes, int n_in,
                              void* d_out, int out_size)
{
    const float* A_in = (const float*)d_in[0];
    const float* B_in = (const float*)d_in[1];
    const float* C_in = (const float*)d_in[2];
    const float* A_W1 = (const float*)d_in[3];
    const float* A_b1 = (const float*)d_in[4];
    const float* A_W2 = (const float*)d_in[5];
    const float* A_b2 = (const float*)d_in[6];
    const float* B_W1 = (const float*)d_in[7];
    const float* B_b1 = (const float*)d_in[8];
    const float* B_W2 = (const float*)d_in[9];
    const float* B_b2 = (const float*)d_in[10];
    const float* C_W1 = (const float*)d_in[11];
    const float* C_b1 = (const float*)d_in[12];
    const float* C_W2 = (const float*)d_in[13];
    const float* C_b2 = (const float*)d_in[14];
    const float* C_W3 = (const float*)d_in[15];
    const float* C_b3 = (const float*)d_in[16];

    float* out = (float*)d_out;

    cudaFuncSetAttribute(contract_kernel,
                         cudaFuncAttributeMaxDynamicSharedMemorySize, SMEM_NEED);

    dim3 g1(NROW, 3);
    hidden_kernel<<<g1, MID>>>(A_in, B_in, C_in, A_W1, A_b1, B_W1, B_b1, C_W1, C_b1);

    dim3 g2(MID / 32, NROW / 32);                  // (8, 12)
    mid_gemm_kernel<<<g2, 256>>>(C_W2, C_b2);

    dim3 g3((NR + 31) / 32, NROW / 32, 3);         // (4, 12, 3)
    final_gemm_kernel<<<g3, 256>>>(A_W2, A_b2, B_W2, B_b2, C_W3, C_b3);

    dim3 grid(NROW / 128, NROW);                   // (3 j-tiles, 384 i)
    contract_kernel<<<grid, 256, SMEM_NEED>>>(out);
}

// round 14
// speedup vs baseline: 1.2815x; 1.0407x over previous
#include <cuda_runtime.h>
#include <cuda_fp16.h>
#include <math.h>
#include <stdint.h>

#define OMEGA 1.5f
#define NROW  384
#define MID   256
#define NR    100     // rank R
#define RP    112     // padded rank (K dim for MMA), 7 x k16

// Factor matrices, row-major padded K: g_X[row*RP + r], r<100 valid, rest 0
__device__ float g_A[NROW * RP];
__device__ float g_B[NROW * RP];
__device__ __half g_Ch[NROW * RP];     // C rounded to fp16

// MLP intermediates
__device__ float g_H[3 * NROW * MID];
__device__ float g_H2[NROW * MID];

// ===========================================================================
// helpers
// ===========================================================================
__device__ __forceinline__ uint32_t smem_u32(const void* p) {
    uint32_t a;
    asm("{ .reg .u64 t; cvta.to.shared.u64 t, %1; cvt.u32.u64 %0, t; }" : "=r"(a) : "l"(p));
    return a;
}
__device__ __forceinline__ void ldsm4(uint32_t addr, uint32_t r[4]) {
    asm volatile("ldmatrix.sync.aligned.m8n8.x4.shared.b16 {%0,%1,%2,%3}, [%4];"
                 : "=r"(r[0]), "=r"(r[1]), "=r"(r[2]), "=r"(r[3]) : "r"(addr));
}
__device__ __forceinline__ void mma16816(float d[4], const uint32_t* a,
                                         uint32_t b0, uint32_t b1) {
    asm volatile("mma.sync.aligned.m16n8k16.row.col.f32.f16.f16.f32 "
                 "{%0,%1,%2,%3}, {%4,%5,%6,%7}, {%8,%9}, {%0,%1,%2,%3};"
                 : "+f"(d[0]), "+f"(d[1]), "+f"(d[2]), "+f"(d[3])
                 : "r"(a[0]), "r"(a[1]), "r"(a[2]), "r"(a[3]), "r"(b0), "r"(b1));
}
__device__ __forceinline__ void cp16(uint32_t dst, const void* src) {
    asm volatile("cp.async.cg.shared.global [%0], [%1], 16;" :: "r"(dst), "l"(src));
}
#define CP_COMMIT() asm volatile("cp.async.commit_group;" ::: "memory")
#define CP_WAIT0()  asm volatile("cp.async.wait_group 0;" ::: "memory")

// ===========================================================================
// Factor networks (precomputed hidden layer, memory GEMMs)
// ===========================================================================
__global__ void hidden_kernel(const float* __restrict__ Ain,
                              const float* __restrict__ Bin,
                              const float* __restrict__ Cin,
                              const float* __restrict__ AW1, const float* __restrict__ Ab1,
                              const float* __restrict__ BW1, const float* __restrict__ Bb1,
                              const float* __restrict__ CW1, const float* __restrict__ Cb1)
{
    const int net = blockIdx.y;
    const int row = blockIdx.x;
    const int t   = threadIdx.x;
    const float x = (net == 0 ? Ain : net == 1 ? Bin : Cin)[row];
    const float* W1 = (net == 0 ? AW1 : net == 1 ? BW1 : CW1);
    const float* b1 = (net == 0 ? Ab1 : net == 1 ? Bb1 : Cb1);
    g_H[(net * NROW + row) * MID + t] = sinf(OMEGA * (x * W1[t] + b1[t]));
}

// 32x32 tile GEMM core, 256 threads, micro 2x2.
__device__ __forceinline__ void gemm32(const float* __restrict__ H,
                                       const float* __restrict__ W,
                                       int rb, int nb, int nout,
                                       float acc[2][2])
{
    __shared__ float sH[32][33];
    __shared__ float sW[32][33];
    const int tid = threadIdx.x;
    const int kk  = tid & 31;
    const int mm  = tid >> 5;        // 0..7
    const int tx  = tid & 15;
    const int ty  = tid >> 4;
    const int m0  = ty * 2;
    const int n0  = tx * 2;

    acc[0][0] = acc[0][1] = acc[1][0] = acc[1][1] = 0.f;

    for (int k0 = 0; k0 < MID; k0 += 32) {
        __syncthreads();
        #pragma unroll
        for (int s = 0; s < 4; s++) {
            const int r = mm + s * 8;
            sH[r][kk] = H[(rb + r) * MID + k0 + kk];
            const int n = nb + r;
            sW[r][kk] = (n < nout) ? W[n * MID + k0 + kk] : 0.f;
        }
        __syncthreads();
        #pragma unroll
        for (int k = 0; k < 32; k++) {
            const float h0 = sH[m0][k], h1 = sH[m0 + 1][k];
            const float w0 = sW[n0][k], w1 = sW[n0 + 1][k];
            acc[0][0] += h0 * w0; acc[0][1] += h0 * w1;
            acc[1][0] += h1 * w0; acc[1][1] += h1 * w1;
        }
    }
}

__global__ void __launch_bounds__(256) mid_gemm_kernel(const float* __restrict__ CW2,
                                                       const float* __restrict__ Cb2)
{
    const int rb = blockIdx.y * 32;
    const int nb = blockIdx.x * 32;
    float acc[2][2];
    gemm32(g_H + 2 * NROW * MID, CW2, rb, nb, MID, acc);
    const int tx = threadIdx.x & 15, ty = threadIdx.x >> 4;
    #pragma unroll
    for (int i = 0; i < 2; i++) {
        const int m = rb + ty * 2 + i;
        #pragma unroll
        for (int j = 0; j < 2; j++) {
            const int n = nb + tx * 2 + j;
            g_H2[m * MID + n] = sinf(OMEGA * (acc[i][j] + Cb2[n]));
        }
    }
}

__global__ void __launch_bounds__(256) final_gemm_kernel(const float* __restrict__ AW2,
                                                         const float* __restrict__ Ab2,
                                                         const float* __restrict__ BW2,
                                                         const float* __restrict__ Bb2,
                                                         const float* __restrict__ CW3,
                                                         const float* __restrict__ Cb3)
{
    const int net = blockIdx.z;
    const int rb  = blockIdx.y * 32;
    const int nb  = blockIdx.x * 32;
    const float* H = (net == 2) ? g_H2 : g_H + net * NROW * MID;
    const float* W = (net == 0) ? AW2 : (net == 1) ? BW2 : CW3;
    const float* b = (net == 0) ? Ab2 : (net == 1) ? Bb2 : Cb3;

    float acc[2][2];
    gemm32(H, W, rb, nb, NR, acc);
    const int tx = threadIdx.x & 15, ty = threadIdx.x >> 4;
    #pragma unroll
    for (int i = 0; i < 2; i++) {
        const int m = rb + ty * 2 + i;
        #pragma unroll
        for (int j = 0; j < 2; j++) {
            const int n = nb + tx * 2 + j;
            if (n < NR) {
                const float v = acc[i][j] + b[n];
                if (net == 0)      g_A[m * RP + n] = v;
                else if (net == 1) g_B[m * RP + n] = v;
                else               g_Ch[m * RP + n] = __float2half_rn(v);
            }
        }
    }
}

// ===========================================================================
// Contraction: HMMA fp16 single pass, A (M) fragments REGISTER-RESIDENT.
// Block 256 = 8 warps (4m x 2n), warp tile 32(j) x 32(k).
// A fragments for all 7 k-steps loaded once (14 ldsm4 = 56 regs); each kb
// iteration issues only B loads: 2 ldsm4 -> 8 MMAs per k-step (4:1 ratio).
// smem: M 30KB + C 2x15KB double-buffered = 61440; 2 CTAs/SM (reg-capped).
// ===========================================================================
#define LDB 240
#define MT  (128 * LDB)              // 30720: [128 x 112] fp16 M tile
#define CT  (64 * LDB)               // 15360: [64 x 112] fp16 C k-tile
#define OFF_M 0
#define OFF_C MT                     // + buf*CT
#define SMEM_NEED (MT + 2 * CT)      // 61440 bytes

__device__ __forceinline__ void prefetch_C(uint32_t sb, int kt, int buf, int tid) {
    const uint32_t dst0 = sb + OFF_C + (uint32_t)(buf * CT);
    #pragma unroll
    for (int it = 0; it < 4; it++) {
        const int idx = tid + it * 256;          // need 0..895 = 64 rows x 14 chunks
        if (idx < 64 * 14) {
            const int row = idx / 14;
            const int ch  = idx % 14;
            const __half* src = g_Ch + (kt * 64 + row) * RP + ch * 8;
            cp16(dst0 + (uint32_t)(row * LDB + ch * 16), src);
        }
    }
}

__global__ void __launch_bounds__(256, 2) contract_kernel(float* __restrict__ out)
{
    extern __shared__ __align__(16) char sm[];
    const uint32_t sbase = smem_u32(sm);

    const int tid  = threadIdx.x;
    const int lane = tid & 31;
    const int wid  = tid >> 5;
    const int i    = blockIdx.y;
    const int jb   = blockIdx.x * 128;

    const int wm = (wid & 3) * 32;    // m (j) offset
    const int wn = (wid >> 2) * 32;   // n (k) offset within 64-k tile

    // prefetch C k-tile 0, then convert M = A[i,:] * B[jb:,:] into fp16
    prefetch_C(sbase, 0, 0, tid);
    CP_COMMIT();

    #pragma unroll
    for (int it = 0; it < 28; it++) {
        const int idx = tid + it * 256;          // 0..7167 = 128 x 56
        const int j  = idx / 56;
        const int pr = idx % 56;
        const int r0 = pr * 2;
        float2 bv = make_float2(0.f, 0.f), av = make_float2(0.f, 0.f);
        if (pr < 50) {
            bv = *reinterpret_cast<const float2*>(&g_B[(jb + j) * RP + r0]);
            av = *reinterpret_cast<const float2*>(&g_A[i * RP + r0]);
        }
        const __half h0 = __float2half_rn(av.x * bv.x);
        const __half h1 = __float2half_rn(av.y * bv.y);
        const uint32_t hv = (uint32_t)__half_as_ushort(h0)
                          | ((uint32_t)__half_as_ushort(h1) << 16);
        *reinterpret_cast<uint32_t*>(sm + OFF_M + (uint32_t)(j * LDB + pr * 4)) = hv;
    }
    CP_WAIT0();
    __syncthreads();

    // fragment lane addresses
    const uint32_t aoff = (uint32_t)((lane & 15) * LDB + (lane >> 4) * 16);
    const uint32_t boff = (uint32_t)(((lane & 7) + ((lane >> 4) << 3)) * LDB
                                     + ((lane >> 3) & 1) * 16);
    const uint32_t mA = sbase + OFF_M + (uint32_t)(wm * LDB) + aoff;

    // load ALL A (M) fragments once: 7 k-steps x 2 ldsm4 = 56 regs
    uint32_t areg[7][8];
    #pragma unroll
    for (int ks = 0; ks < 7; ks++) {
        ldsm4(mA + ks * 32, areg[ks]);
        ldsm4(mA + 16 * LDB + ks * 32, areg[ks] + 4);
    }

    float acc[8][4];
    #pragma unroll
    for (int t = 0; t < 8; t++)
        #pragma unroll
        for (int q = 0; q < 4; q++) acc[t][q] = 0.f;

    const int g  = lane >> 2;
    const int c2 = (lane & 3) * 2;

    for (int kb = 0; kb < 6; kb++) {
        // start async load of next C k-tile (overlaps this kb's MMAs)
        if (kb < 5) { prefetch_C(sbase, kb + 1, (kb + 1) & 1, tid); CP_COMMIT(); }

        const uint32_t Bb = sbase + OFF_C + (uint32_t)((kb & 1) * CT)
                           + (uint32_t)(wn * LDB) + boff;

        #pragma unroll
        for (int ks = 0; ks < 7; ks++) {
            uint32_t bh[8];
            ldsm4(Bb + ks * 32, bh);
            ldsm4(Bb + 16 * LDB + ks * 32, bh + 4);
            #pragma unroll
            for (int nt = 0; nt < 4; nt++) {
                const uint32_t b0 = bh[nt * 2], b1 = bh[nt * 2 + 1];
                mma16816(acc[nt],     areg[ks],     b0, b1);
                mma16816(acc[4 + nt], areg[ks] + 4, b0, b1);
            }
        }

        // store this 64-k tile, reset acc
        #pragma unroll
        for (int mt = 0; mt < 2; mt++) {
            #pragma unroll
            for (int nt = 0; nt < 4; nt++) {
                float* p = out + ((size_t)i * NROW + (size_t)(jb + wm + mt * 16 + g)) * NROW
                               + (size_t)(kb * 64 + wn + nt * 8 + c2);
                float* a = acc[mt * 4 + nt];
                *reinterpret_cast<float2*>(p) = make_float2(a[0], a[1]);
                *reinterpret_cast<float2*>(p + (size_t)8 * NROW) = make_float2(a[2], a[3]);
                a[0] = a[1] = a[2] = a[3] = 0.f;
            }
        }

        if (kb < 5) { CP_WAIT0(); __syncthreads(); }
    }
}

// ===========================================================================
// kernel_launch
// ===========================================================================
extern "C" void kernel_launch(void* const* d_in, const int* in_sizes, int n_in,
                              void* d_out, int out_size)
{
    const float* A_in = (const float*)d_in[0];
    const float* B_in = (const float*)d_in[1];
    const float* C_in = (const float*)d_in[2];
    const float* A_W1 = (const float*)d_in[3];
    const float* A_b1 = (const float*)d_in[4];
    const float* A_W2 = (const float*)d_in[5];
    const float* A_b2 = (const float*)d_in[6];
    const float* B_W1 = (const float*)d_in[7];
    const float* B_b1 = (const float*)d_in[8];
    const float* B_W2 = (const float*)d_in[9];
    const float* B_b2 = (const float*)d_in[10];
    const float* C_W1 = (const float*)d_in[11];
    const float* C_b1 = (const float*)d_in[12];
    const float* C_W2 = (const float*)d_in[13];
    const float* C_b2 = (const float*)d_in[14];
    const float* C_W3 = (const float*)d_in[15];
    const float* C_b3 = (const float*)d_in[16];

    float* out = (float*)d_out;

    cudaFuncSetAttribute(contract_kernel,
                         cudaFuncAttributeMaxDynamicSharedMemorySize, SMEM_NEED);

    dim3 g1(NROW, 3);
    hidden_kernel<<<g1, MID>>>(A_in, B_in, C_in, A_W1, A_b1, B_W1, B_b1, C_W1, C_b1);

    dim3 g2(MID / 32, NROW / 32);                  // (8, 12)
    mid_gemm_kernel<<<g2, 256>>>(C_W2, C_b2);

    dim3 g3((NR + 31) / 32, NROW / 32, 3);         // (4, 12, 3)
    final_gemm_kernel<<<g3, 256>>>(A_W2, A_b2, B_W2, B_b2, C_W3, C_b3);

    dim3 grid(NROW / 128, NROW);                   // (3 j-tiles, 384 i)
    contract_kernel<<<grid, 256, SMEM_NEED>>>(out);
}

// round 15
// speedup vs baseline: 1.3369x; 1.0432x over previous
#include <cuda_runtime.h>
#include <cuda_fp16.h>
#include <math.h>
#include <stdint.h>

#define OMEGA 1.5f
#define NROW  384
#define MID   256
#define NR    100     // rank R
#define RP    112     // padded rank (K dim for MMA), 7 x k16

// Factor matrices, row-major padded K: g_X[row*RP + r], r<100 valid, rest 0
__device__ float g_A[NROW * RP];
__device__ float g_B[NROW * RP];
__device__ __half g_Ch[NROW * RP];     // C rounded to fp16

// MLP intermediates
__device__ float g_H[3 * NROW * MID];
__device__ float g_H2[NROW * MID];

// ===========================================================================
// helpers
// ===========================================================================
__device__ __forceinline__ uint32_t smem_u32(const void* p) {
    uint32_t a;
    asm("{ .reg .u64 t; cvta.to.shared.u64 t, %1; cvt.u32.u64 %0, t; }" : "=r"(a) : "l"(p));
    return a;
}
__device__ __forceinline__ void ldsm4(uint32_t addr, uint32_t r[4]) {
    asm volatile("ldmatrix.sync.aligned.m8n8.x4.shared.b16 {%0,%1,%2,%3}, [%4];"
                 : "=r"(r[0]), "=r"(r[1]), "=r"(r[2]), "=r"(r[3]) : "r"(addr));
}
__device__ __forceinline__ void mma16816(float d[4], const uint32_t* a,
                                         uint32_t b0, uint32_t b1) {
    asm volatile("mma.sync.aligned.m16n8k16.row.col.f32.f16.f16.f32 "
                 "{%0,%1,%2,%3}, {%4,%5,%6,%7}, {%8,%9}, {%0,%1,%2,%3};"
                 : "+f"(d[0]), "+f"(d[1]), "+f"(d[2]), "+f"(d[3])
                 : "r"(a[0]), "r"(a[1]), "r"(a[2]), "r"(a[3]), "r"(b0), "r"(b1));
}
__device__ __forceinline__ void cp16(uint32_t dst, const void* src) {
    asm volatile("cp.async.cg.shared.global [%0], [%1], 16;" :: "r"(dst), "l"(src));
}
#define CP_COMMIT() asm volatile("cp.async.commit_group;" ::: "memory")
#define CP_WAIT0()  asm volatile("cp.async.wait_group 0;" ::: "memory")

// ===========================================================================
// Factor networks
// ===========================================================================
__global__ void hidden_kernel(const float* __restrict__ Ain,
                              const float* __restrict__ Bin,
                              const float* __restrict__ Cin,
                              const float* __restrict__ AW1, const float* __restrict__ Ab1,
                              const float* __restrict__ BW1, const float* __restrict__ Bb1,
                              const float* __restrict__ CW1, const float* __restrict__ Cb1)
{
    const int net = blockIdx.y;
    const int row = blockIdx.x;
    const int t   = threadIdx.x;
    const float x = (net == 0 ? Ain : net == 1 ? Bin : Cin)[row];
    const float* W1 = (net == 0 ? AW1 : net == 1 ? BW1 : CW1);
    const float* b1 = (net == 0 ? Ab1 : net == 1 ? Bb1 : Cb1);
    g_H[(net * NROW + row) * MID + t] = sinf(OMEGA * (x * W1[t] + b1[t]));
}

// 32x32 tile GEMM core, 256 threads, micro 2x2.
__device__ __forceinline__ void gemm32(const float* __restrict__ H,
                                       const float* __restrict__ W,
                                       int rb, int nb, int nout,
                                       float acc[2][2])
{
    __shared__ float sH[32][33];
    __shared__ float sW[32][33];
    const int tid = threadIdx.x;
    const int kk  = tid & 31;
    const int mm  = tid >> 5;        // 0..7
    const int tx  = tid & 15;
    const int ty  = tid >> 4;
    const int m0  = ty * 2;
    const int n0  = tx * 2;

    acc[0][0] = acc[0][1] = acc[1][0] = acc[1][1] = 0.f;

    for (int k0 = 0; k0 < MID; k0 += 32) {
        __syncthreads();
        #pragma unroll
        for (int s = 0; s < 4; s++) {
            const int r = mm + s * 8;
            sH[r][kk] = H[(rb + r) * MID + k0 + kk];
            const int n = nb + r;
            sW[r][kk] = (n < nout) ? W[n * MID + k0 + kk] : 0.f;
        }
        __syncthreads();
        #pragma unroll
        for (int k = 0; k < 32; k++) {
            const float h0 = sH[m0][k], h1 = sH[m0 + 1][k];
            const float w0 = sW[n0][k], w1 = sW[n0 + 1][k];
            acc[0][0] += h0 * w0; acc[0][1] += h0 * w1;
            acc[1][0] += h1 * w0; acc[1][1] += h1 * w1;
        }
    }
}

// Fused: z=0 -> A final, z=1 -> B final, z=2 -> C middle layer.
// Grid (8, 12, 3); final nets use only bx<4.
__global__ void __launch_bounds__(256) fused_mid_final_kernel(
    const float* __restrict__ AW2, const float* __restrict__ Ab2,
    const float* __restrict__ BW2, const float* __restrict__ Bb2,
    const float* __restrict__ CW2, const float* __restrict__ Cb2)
{
    const int net = blockIdx.z;
    const int rb  = blockIdx.y * 32;
    const int nb  = blockIdx.x * 32;
    const int tx = threadIdx.x & 15, ty = threadIdx.x >> 4;
    float acc[2][2];

    if (net == 2) {
        gemm32(g_H + 2 * NROW * MID, CW2, rb, nb, MID, acc);
        #pragma unroll
        for (int i = 0; i < 2; i++) {
            const int m = rb + ty * 2 + i;
            #pragma unroll
            for (int j = 0; j < 2; j++) {
                const int n = nb + tx * 2 + j;
                g_H2[m * MID + n] = sinf(OMEGA * (acc[i][j] + Cb2[n]));
            }
        }
    } else {
        if (blockIdx.x >= 4) return;   // whole block exits: no barrier divergence
        const float* H = g_H + net * NROW * MID;
        const float* W = net ? BW2 : AW2;
        const float* b = net ? Bb2 : Ab2;
        gemm32(H, W, rb, nb, NR, acc);
        #pragma unroll
        for (int i = 0; i < 2; i++) {
            const int m = rb + ty * 2 + i;
            #pragma unroll
            for (int j = 0; j < 2; j++) {
                const int n = nb + tx * 2 + j;
                if (n < NR) {
                    const float v = acc[i][j] + b[n];
                    if (net == 0) g_A[m * RP + n] = v;
                    else          g_B[m * RP + n] = v;
                }
            }
        }
    }
}

// C final layer -> g_Ch (fp16)
__global__ void __launch_bounds__(256) final_c_kernel(const float* __restrict__ CW3,
                                                      const float* __restrict__ Cb3)
{
    const int rb = blockIdx.y * 32;
    const int nb = blockIdx.x * 32;
    float acc[2][2];
    gemm32(g_H2, CW3, rb, nb, NR, acc);
    const int tx = threadIdx.x & 15, ty = threadIdx.x >> 4;
    #pragma unroll
    for (int i = 0; i < 2; i++) {
        const int m = rb + ty * 2 + i;
        #pragma unroll
        for (int j = 0; j < 2; j++) {
            const int n = nb + tx * 2 + j;
            if (n < NR) g_Ch[m * RP + n] = __float2half_rn(acc[i][j] + Cb3[n]);
        }
    }
}

// ===========================================================================
// Contraction: HMMA fp16 single pass, A register-resident, B reg double-buffer.
// Block 256 = 8 warps (4m x 2n), warp tile 32(j) x 32(k).
// Per k-step: 2 ldsm4 (next B, overlapped) -> 8 MMAs (current B).
// smem: M 30KB + C 2x15KB double-buffered = 61440; 2 CTAs/SM.
// ===========================================================================
#define LDB 240
#define MT  (128 * LDB)              // 30720: [128 x 112] fp16 M tile
#define CT  (64 * LDB)               // 15360: [64 x 112] fp16 C k-tile
#define OFF_M 0
#define OFF_C MT                     // + buf*CT
#define SMEM_NEED (MT + 2 * CT)      // 61440 bytes

__device__ __forceinline__ void prefetch_C(uint32_t sb, int kt, int buf, int tid) {
    const uint32_t dst0 = sb + OFF_C + (uint32_t)(buf * CT);
    #pragma unroll
    for (int it = 0; it < 4; it++) {
        const int idx = tid + it * 256;          // need 0..895 = 64 rows x 14 chunks
        if (idx < 64 * 14) {
            const int row = idx / 14;
            const int ch  = idx % 14;
            const __half* src = g_Ch + (kt * 64 + row) * RP + ch * 8;
            cp16(dst0 + (uint32_t)(row * LDB + ch * 16), src);
        }
    }
}

__global__ void __launch_bounds__(256, 2) contract_kernel(float* __restrict__ out)
{
    extern __shared__ __align__(16) char sm[];
    const uint32_t sbase = smem_u32(sm);

    const int tid  = threadIdx.x;
    const int lane = tid & 31;
    const int wid  = tid >> 5;
    const int i    = blockIdx.y;
    const int jb   = blockIdx.x * 128;

    const int wm = (wid & 3) * 32;    // m (j) offset
    const int wn = (wid >> 2) * 32;   // n (k) offset within 64-k tile

    // prefetch C k-tile 0, then convert M = A[i,:] * B[jb:,:] into fp16
    prefetch_C(sbase, 0, 0, tid);
    CP_COMMIT();

    #pragma unroll
    for (int it = 0; it < 28; it++) {
        const int idx = tid + it * 256;          // 0..7167 = 128 x 56
        const int j  = idx / 56;
        const int pr = idx % 56;
        const int r0 = pr * 2;
        float2 bv = make_float2(0.f, 0.f), av = make_float2(0.f, 0.f);
        if (pr < 50) {
            bv = *reinterpret_cast<const float2*>(&g_B[(jb + j) * RP + r0]);
            av = *reinterpret_cast<const float2*>(&g_A[i * RP + r0]);
        }
        const __half h0 = __float2half_rn(av.x * bv.x);
        const __half h1 = __float2half_rn(av.y * bv.y);
        const uint32_t hv = (uint32_t)__half_as_ushort(h0)
                          | ((uint32_t)__half_as_ushort(h1) << 16);
        *reinterpret_cast<uint32_t*>(sm + OFF_M + (uint32_t)(j * LDB + pr * 4)) = hv;
    }
    CP_WAIT0();
    __syncthreads();

    // fragment lane addresses
    const uint32_t aoff = (uint32_t)((lane & 15) * LDB + (lane >> 4) * 16);
    const uint32_t boff = (uint32_t)(((lane & 7) + ((lane >> 4) << 3)) * LDB
                                     + ((lane >> 3) & 1) * 16);
    const uint32_t mA = sbase + OFF_M + (uint32_t)(wm * LDB) + aoff;

    // load ALL A (M) fragments once: 7 k-steps x 2 ldsm4 = 56 regs
    uint32_t areg[7][8];
    #pragma unroll
    for (int ks = 0; ks < 7; ks++) {
        ldsm4(mA + ks * 32, areg[ks]);
        ldsm4(mA + 16 * LDB + ks * 32, areg[ks] + 4);
    }

    float acc[8][4];
    #pragma unroll
    for (int t = 0; t < 8; t++)
        #pragma unroll
        for (int q = 0; q < 4; q++) acc[t][q] = 0.f;

    const int g  = lane >> 2;
    const int c2 = (lane & 3) * 2;

    for (int kb = 0; kb < 6; kb++) {
        // start async load of next C k-tile (overlaps this kb's MMAs)
        if (kb < 5) { prefetch_C(sbase, kb + 1, (kb + 1) & 1, tid); CP_COMMIT(); }

        const uint32_t Bb = sbase + OFF_C + (uint32_t)((kb & 1) * CT)
                           + (uint32_t)(wn * LDB) + boff;

        // B register double-buffer: preload ks=0, then overlap ks+1 load
        uint32_t bh[2][8];
        ldsm4(Bb, bh[0]);
        ldsm4(Bb + 16 * LDB, bh[0] + 4);

        #pragma unroll
        for (int ks = 0; ks < 7; ks++) {
            const int cur = ks & 1;
            if (ks < 6) {
                ldsm4(Bb + (ks + 1) * 32, bh[cur ^ 1]);
                ldsm4(Bb + 16 * LDB + (ks + 1) * 32, bh[cur ^ 1] + 4);
            }
            #pragma unroll
            for (int nt = 0; nt < 4; nt++) {
                const uint32_t b0 = bh[cur][nt * 2], b1 = bh[cur][nt * 2 + 1];
                mma16816(acc[nt],     areg[ks],     b0, b1);
                mma16816(acc[4 + nt], areg[ks] + 4, b0, b1);
            }
        }

        // store this 64-k tile, reset acc
        #pragma unroll
        for (int mt = 0; mt < 2; mt++) {
            #pragma unroll
            for (int nt = 0; nt < 4; nt++) {
                float* p = out + ((size_t)i * NROW + (size_t)(jb + wm + mt * 16 + g)) * NROW
                               + (size_t)(kb * 64 + wn + nt * 8 + c2);
                float* a = acc[mt * 4 + nt];
                *reinterpret_cast<float2*>(p) = make_float2(a[0], a[1]);
                *reinterpret_cast<float2*>(p + (size_t)8 * NROW) = make_float2(a[2], a[3]);
                a[0] = a[1] = a[2] = a[3] = 0.f;
            }
        }

        if (kb < 5) { CP_WAIT0(); __syncthreads(); }
    }
}

// ===========================================================================
// kernel_launch
// ===========================================================================
extern "C" void kernel_launch(void* const* d_in, const int* in_sizes, int n_in,
                              void* d_out, int out_size)
{
    const float* A_in = (const float*)d_in[0];
    const float* B_in = (const float*)d_in[1];
    const float* C_in = (const float*)d_in[2];
    const float* A_W1 = (const float*)d_in[3];
    const float* A_b1 = (const float*)d_in[4];
    const float* A_W2 = (const float*)d_in[5];
    const float* A_b2 = (const float*)d_in[6];
    const float* B_W1 = (const float*)d_in[7];
    const float* B_b1 = (const float*)d_in[8];
    const float* B_W2 = (const float*)d_in[9];
    const float* B_b2 = (const float*)d_in[10];
    const float* C_W1 = (const float*)d_in[11];
    const float* C_b1 = (const float*)d_in[12];
    const float* C_W2 = (const float*)d_in[13];
    const float* C_b2 = (const float*)d_in[14];
    const float* C_W3 = (const float*)d_in[15];
    const float* C_b3 = (const float*)d_in[16];

    float* out = (float*)d_out;

    cudaFuncSetAttribute(contract_kernel,
                         cudaFuncAttributeMaxDynamicSharedMemorySize, SMEM_NEED);

    dim3 g1(NROW, 3);
    hidden_kernel<<<g1, MID>>>(A_in, B_in, C_in, A_W1, A_b1, B_W1, B_b1, C_W1, C_b1);

    dim3 g2(8, 12, 3);                             // A-final, B-final, C-mid fused
    fused_mid_final_kernel<<<g2, 256>>>(A_W2, A_b2, B_W2, B_b2, C_W2, C_b2);

    dim3 g3(4, 12);                                // C final
    final_c_kernel<<<g3, 256>>>(C_W3, C_b3);

    dim3 grid(NROW / 128, NROW);                   // (3 j-tiles, 384 i)
    contract_kernel<<<grid, 256, SMEM_NEED>>>(out);
}